// round 8
// baseline (speedup 1.0000x reference)
#include <cuda_runtime.h>
#include <cstdint>

// AI4DEM coupling_backward: 3x3 tent-spline gather, 4096x4096 periodic grid.
// Inputs: xp, yp, x_grid(unused), y_grid(unused), vx, vy, Fx, Fy, mask
// Output: 5 planes [alpha, alpha_u, alpha_v, Fx, Fy], each 4096*4096 f32.
//
//   per tap: w = max(0,1-|xp_src - x_dst|) * max(0,1-|yp_src - y_dst|)
//   out     = mask_dst * VP * sum(w * field_src)     (mask at DESTINATION)
//
// R8: double-buffered cp.async pipeline. Each block walks 4 consecutive
// 8-row tiles in y; prefetch of tile i+1 (cp.async.cg into the other smem
// buffer) is issued BEFORE computing tile i, and drained after. The DRAM
// stream is continuous instead of bursty, and the stage-latency bubble is
// paid once per 4 tiles. 65.3 KB dynamic smem -> 3 blocks/SM; low occupancy
// is fine because warps no longer wait on DRAM, only smem/FMA.

#define NXD   4096
#define MASKW 4095

#define BLK_T    128          // threads per block
#define OUT_ROWS 8            // output rows per tile
#define SRC_ROWS 10           // OUT_ROWS + 2 halo rows
#define ROWW     136          // 4 pad | 128 main | 4 pad  (floats)
#define ROWVECS  34           // float4s per field-row
#define VECS_PER_FIELD (SRC_ROWS * ROWVECS)          // 340
#define BUF_FLOATS (6 * SRC_ROWS * ROWW)             // 8160
#define NT       4            // tiles per block

#define SMF(B, f, r, c) (B)[((f) * SRC_ROWS + (r)) * ROWW + (c)]

__device__ __forceinline__ void cpa16(uint32_t saddr, const float* g) {
    asm volatile("cp.async.cg.shared.global [%0], [%1], 16;\n"
                 :: "r"(saddr), "l"(g));
}

__device__ __forceinline__ float tent(float d) {
    return fmaxf(1.0f - fabsf(d), 0.0f);
}

__device__ __forceinline__ constexpr int kmin_of(int s) { return (s - 2 > 0) ? (s - 2) : 0; }
__device__ __forceinline__ constexpr int kmax_of(int s) { return (s < 3) ? s : 3; }

__device__ __forceinline__ void stage_tile(float* B, int y0b, int xb0, int t,
                                           const float* __restrict__ xp,
                                           const float* __restrict__ yp,
                                           const float* __restrict__ vx,
                                           const float* __restrict__ vy,
                                           const float* __restrict__ Fx,
                                           const float* __restrict__ Fy)
{
    const float* fptr[6] = {xp, yp, vx, vy, Fx, Fy};
    #pragma unroll
    for (int f = 0; f < 6; ++f) {
        const float* base = fptr[f];
        for (int j = t; j < VECS_PER_FIELD; j += BLK_T) {
            int rr = j / ROWVECS;                     // 0..9
            int v  = j - rr * ROWVECS;                // 0..33
            int gy = (y0b - 1 + rr) & MASKW;
            int gx = (xb0 - 4 + (v << 2)) & MASKW;    // 16B-aligned, wraps whole
            uint32_t sa = (uint32_t)__cvta_generic_to_shared(&SMF(B, f, rr, v << 2));
            cpa16(sa, base + ((size_t)gy << 12) + gx);
        }
    }
}

__global__ void __launch_bounds__(BLK_T, 3)
ai4dem_kernel(const float* __restrict__ xp, const float* __restrict__ yp,
              const float* __restrict__ vx, const float* __restrict__ vy,
              const float* __restrict__ Fx, const float* __restrict__ Fy,
              const float* __restrict__ mk, float* __restrict__ out)
{
    const float VP = 3.1415f / 6.0f;

    extern __shared__ float smem_dyn[];
    float* bufs[2] = {smem_dyn, smem_dyn + BUF_FLOATS};

    const int t   = threadIdx.x;
    const int bx  = blockIdx.x & 31;          // 32 col-blocks (fastest: L2 row locality)
    const int yg  = blockIdx.x >> 5;          // 128 y-groups of NT tiles
    const int xb0 = bx << 7;                  // block's first col

    const int tx = t & 31;                    // col quad within block
    const int ty = t >> 5;                    // row pair within tile (0..3)
    const int xl = tx << 2;                   // local col offset
    const int xb = xb0 + xl;                  // global base col
    const float xk0 = (float)xb;
    const float xdst[4] = {xk0, xk0 + 1.0f, xk0 + 2.0f, xk0 + 3.0f};
    const size_t P = (size_t)NXD * NXD;

    // prologue: stage first tile
    stage_tile(bufs[0], yg * (NT * OUT_ROWS), xb0, t, xp, yp, vx, vy, Fx, Fy);
    asm volatile("cp.async.commit_group;\n" ::: "memory");
    asm volatile("cp.async.wait_group 0;\n" ::: "memory");
    __syncthreads();

    int cur = 0;
    #pragma unroll 1
    for (int it = 0; it < NT; ++it) {
        const int y0b = yg * (NT * OUT_ROWS) + it * OUT_ROWS;

        // prefetch next tile into the other buffer (overlaps with compute)
        if (it + 1 < NT) {
            stage_tile(bufs[cur ^ 1], y0b + OUT_ROWS, xb0, t, xp, yp, vx, vy, Fx, Fy);
            asm volatile("cp.async.commit_group;\n" ::: "memory");
        }

        const float* B = bufs[cur];
        const int y0 = y0b + (ty << 1);
        const float fy0 = (float)y0;
        const float fy1 = (float)(y0 + 1);

        float aA[2][4] = {{0.f,0.f,0.f,0.f},{0.f,0.f,0.f,0.f}};
        float aU[2][4] = {{0.f,0.f,0.f,0.f},{0.f,0.f,0.f,0.f}};
        float aV[2][4] = {{0.f,0.f,0.f,0.f},{0.f,0.f,0.f,0.f}};
        float aX[2][4] = {{0.f,0.f,0.f,0.f},{0.f,0.f,0.f,0.f}};
        float aY[2][4] = {{0.f,0.f,0.f,0.f},{0.f,0.f,0.f,0.f}};

        #pragma unroll
        for (int r = 0; r < 4; ++r) {             // src rows y0-1 .. y0+2
            const int sr = (ty << 1) + r;         // smem row 0..9
            const int dmin = (r == 3) ? 1 : 0;
            const int dmax = (r == 0) ? 0 : 1;

            float ny[2][6];
            float nx[12];
            {
                float4 qx = *reinterpret_cast<const float4*>(&SMF(B, 0, sr, 4 + xl));
                float xl0 = SMF(B, 0, sr, 3 + xl), xr0 = SMF(B, 0, sr, 8 + xl);
                float4 qy = *reinterpret_cast<const float4*>(&SMF(B, 1, sr, 4 + xl));
                float yl0 = SMF(B, 1, sr, 3 + xl), yr0 = SMF(B, 1, sr, 8 + xl);
                float xps[6] = {xl0, qx.x, qx.y, qx.z, qx.w, xr0};
                float yps[6] = {yl0, qy.x, qy.y, qy.z, qy.w, yr0};
                int idx = 0;
                #pragma unroll
                for (int s = 0; s < 6; ++s) {
                    #pragma unroll
                    for (int d = dmin; d <= dmax; ++d)
                        ny[d][s] = tent(yps[s] - (d ? fy1 : fy0));
                    #pragma unroll
                    for (int k = kmin_of(s); k <= kmax_of(s); ++k)
                        nx[idx++] = tent(xps[s] - xdst[k]);
                }
            }

            {
                float4 qu = *reinterpret_cast<const float4*>(&SMF(B, 2, sr, 4 + xl));
                float ul = SMF(B, 2, sr, 3 + xl), ur = SMF(B, 2, sr, 8 + xl);
                float4 qv = *reinterpret_cast<const float4*>(&SMF(B, 3, sr, 4 + xl));
                float vl = SMF(B, 3, sr, 3 + xl), vr = SMF(B, 3, sr, 8 + xl);
                float vxs[6] = {ul, qu.x, qu.y, qu.z, qu.w, ur};
                float vys[6] = {vl, qv.x, qv.y, qv.z, qv.w, vr};
                int idx = 0;
                #pragma unroll
                for (int s = 0; s < 6; ++s) {
                    const int i0 = idx;
                    #pragma unroll
                    for (int d = dmin; d <= dmax; ++d) {
                        float n  = ny[d][s];
                        float tu = n * vxs[s];
                        float tv = n * vys[s];
                        int ii = i0;
                        #pragma unroll
                        for (int k = kmin_of(s); k <= kmax_of(s); ++k, ++ii) {
                            float w = nx[ii];
                            aA[d][k] = fmaf(w, n,  aA[d][k]);
                            aU[d][k] = fmaf(w, tu, aU[d][k]);
                            aV[d][k] = fmaf(w, tv, aV[d][k]);
                        }
                    }
                    idx += kmax_of(s) - kmin_of(s) + 1;
                }
            }

            {
                float4 qa = *reinterpret_cast<const float4*>(&SMF(B, 4, sr, 4 + xl));
                float al = SMF(B, 4, sr, 3 + xl), ar = SMF(B, 4, sr, 8 + xl);
                float4 qb = *reinterpret_cast<const float4*>(&SMF(B, 5, sr, 4 + xl));
                float bl = SMF(B, 5, sr, 3 + xl), br = SMF(B, 5, sr, 8 + xl);
                float fxs[6] = {al, qa.x, qa.y, qa.z, qa.w, ar};
                float fys[6] = {bl, qb.x, qb.y, qb.z, qb.w, br};
                int idx = 0;
                #pragma unroll
                for (int s = 0; s < 6; ++s) {
                    const int i0 = idx;
                    #pragma unroll
                    for (int d = dmin; d <= dmax; ++d) {
                        float n   = ny[d][s];
                        float txv = n * fxs[s];
                        float tyv = n * fys[s];
                        int ii = i0;
                        #pragma unroll
                        for (int k = kmin_of(s); k <= kmax_of(s); ++k, ++ii) {
                            float w = nx[ii];
                            aX[d][k] = fmaf(w, txv, aX[d][k]);
                            aY[d][k] = fmaf(w, tyv, aY[d][k]);
                        }
                    }
                    idx += kmax_of(s) - kmin_of(s) + 1;
                }
            }
        }

        // mask (at destination) * VP, then store 5 planes
        #pragma unroll
        for (int d = 0; d < 2; ++d) {
            size_t o = ((size_t)(y0 + d) << 12) + xb;
            float4 mq = *reinterpret_cast<const float4*>(mk + o);
            float md[4] = {mq.x * VP, mq.y * VP, mq.z * VP, mq.w * VP};

            #pragma unroll
            for (int k = 0; k < 4; ++k) {
                aA[d][k] *= md[k]; aU[d][k] *= md[k]; aV[d][k] *= md[k];
                aX[d][k] *= md[k]; aY[d][k] *= md[k];
            }

            *reinterpret_cast<float4*>(out + o)         = make_float4(aA[d][0], aA[d][1], aA[d][2], aA[d][3]);
            *reinterpret_cast<float4*>(out + P + o)     = make_float4(aU[d][0], aU[d][1], aU[d][2], aU[d][3]);
            *reinterpret_cast<float4*>(out + 2 * P + o) = make_float4(aV[d][0], aV[d][1], aV[d][2], aV[d][3]);
            *reinterpret_cast<float4*>(out + 3 * P + o) = make_float4(aX[d][0], aX[d][1], aX[d][2], aX[d][3]);
            *reinterpret_cast<float4*>(out + 4 * P + o) = make_float4(aY[d][0], aY[d][1], aY[d][2], aY[d][3]);
        }

        // drain prefetch (had the whole compute phase to complete)
        asm volatile("cp.async.wait_group 0;\n" ::: "memory");
        __syncthreads();
        cur ^= 1;
    }
}

extern "C" void kernel_launch(void* const* d_in, const int* in_sizes, int n_in,
                              void* d_out, int out_size)
{
    const float* xp = (const float*)d_in[0];
    const float* yp = (const float*)d_in[1];
    // d_in[2] = x_grid, d_in[3] = y_grid: analytic (x, y), not needed.
    const float* vx = (const float*)d_in[4];
    const float* vy = (const float*)d_in[5];
    const float* Fx = (const float*)d_in[6];
    const float* Fy = (const float*)d_in[7];
    const float* mk = (const float*)d_in[8];
    float* out = (float*)d_out;

    const int smem_bytes = 2 * BUF_FLOATS * (int)sizeof(float);   // 65,280
    cudaFuncSetAttribute(ai4dem_kernel,
                         cudaFuncAttributeMaxDynamicSharedMemorySize, smem_bytes);

    // 32 col-blocks x 128 y-groups; each block: 128 cols x 32 rows (4 tiles)
    ai4dem_kernel<<<32 * 128, BLK_T, smem_bytes>>>(xp, yp, vx, vy, Fx, Fy, mk, out);
}